// round 1
// baseline (speedup 1.0000x reference)
#include <cuda_runtime.h>

#define B_    16
#define N_    400
#define P_    200
#define E_D   200
#define A_D   128
#define H_    8
#define PT    8      // pathways per block in kernel B
#define NT    64     // gene chunk in scores phase
#define PRJPAD 130   // padded row (floats) for proj chunk in smem

// proj scratch: (B*N, A) fp32
__device__ float g_proj[B_ * N_ * A_D];

typedef unsigned long long u64;

__device__ __forceinline__ u64 pack2(float x, float y) {
    u64 r; asm("mov.b64 %0, {%1, %2};" : "=l"(r) : "f"(x), "f"(y)); return r;
}
__device__ __forceinline__ void unpack2(u64 v, float& x, float& y) {
    asm("mov.b64 {%0, %1}, %2;" : "=f"(x), "=f"(y) : "l"(v));
}
__device__ __forceinline__ u64 fma2(u64 a, u64 b, u64 c) {
    u64 d; asm("fma.rn.f32x2 %0, %1, %2, %3;" : "=l"(d) : "l"(a), "l"(b), "l"(c)); return d;
}
__device__ __forceinline__ u64 add2(u64 a, u64 b) {
    u64 d; asm("add.rn.f32x2 %0, %1, %2;" : "=l"(d) : "l"(a), "l"(b)); return d;
}
__device__ __forceinline__ float tanh_ap(float x) {
    float y; asm("tanh.approx.f32 %0, %1;" : "=f"(y) : "f"(x)); return y;
}
__device__ __forceinline__ u64 tanh2(u64 v) {
    float x, y; unpack2(v, x, y);
    return pack2(tanh_ap(x), tanh_ap(y));
}

// ---------------------------------------------------------------------------
// Kernel A: proj[row, a] = sum_e emb_gene[omc[row], e] * W0[e, a] + b0[a]
// 8 rows per block, 128 threads (one per a). E rows staged transposed in smem
// so compute reads are 2x LDS.128 broadcast per e.
// ---------------------------------------------------------------------------
__global__ __launch_bounds__(128) void kA(
    const int* __restrict__ omc, const float* __restrict__ eg,
    const float* __restrict__ W0, const float* __restrict__ b0)
{
    __shared__ float EsT[E_D * 8];   // [e][r]
    __shared__ int idxs[8];
    const int r0 = blockIdx.x * 8;
    const int t  = threadIdx.x;

    if (t < 8) idxs[t] = omc[r0 + t];
    __syncthreads();

    for (int i = t; i < 8 * E_D; i += 128) {
        int r = i / E_D, e = i - r * E_D;
        EsT[e * 8 + r] = eg[(long)idxs[r] * E_D + e];
    }
    __syncthreads();

    const int a = t;
    float acc[8];
    const float bias = b0[a];
#pragma unroll
    for (int r = 0; r < 8; r++) acc[r] = bias;

    const float4* E4 = (const float4*)EsT;
#pragma unroll 2
    for (int e = 0; e < E_D; e++) {
        float w  = W0[e * A_D + a];
        float4 u = E4[e * 2];
        float4 v = E4[e * 2 + 1];
        acc[0] = fmaf(u.x, w, acc[0]);
        acc[1] = fmaf(u.y, w, acc[1]);
        acc[2] = fmaf(u.z, w, acc[2]);
        acc[3] = fmaf(u.w, w, acc[3]);
        acc[4] = fmaf(v.x, w, acc[4]);
        acc[5] = fmaf(v.y, w, acc[5]);
        acc[6] = fmaf(v.z, w, acc[6]);
        acc[7] = fmaf(v.w, w, acc[7]);
    }
#pragma unroll
    for (int r = 0; r < 8; r++)
        g_proj[(long)(r0 + r) * A_D + a] = acc[r];
}

// ---------------------------------------------------------------------------
// Kernel B (fused): block = (b, 8-pathway tile), 256 threads = 8 warps.
// Phase 1: scores[p][h][n] = tanh(proj[n]+Ep[p]) @ Wb + bb (f32x2 FMAs)
// Phase 2: per-warp softmax over n per head, sum heads -> attn[p][n]
// Phase 3: out[b,p,:] = sum_n attn[p][n] * emb_gene[omc[b,n], :]
//
// SMEM (floats):
//   [0,      25600) scores (PT*H*N)     -> reused as E chunk (100x200) in ph.3
//   [25600,  33920) proj chunk NT*130   -> reused as attn (PT*400) in ph.2/3
//   [33920,  34944) Ep (PT*A)
//   [34944,  35968) Wb pairs (64*8 float2)
//   [35968,  35976) bb
//   [35976,  36076) idx staging (100 ints)
// = 36076 floats = 144304 bytes
// ---------------------------------------------------------------------------
#define SMEM_B_FLOATS 36080
#define SMEM_B_BYTES  (SMEM_B_FLOATS * 4)

extern __shared__ float smemB[];

__global__ __launch_bounds__(256, 1) void kB(
    const int* __restrict__ omc, const int* __restrict__ ptw,
    const float* __restrict__ eg, const float* __restrict__ ept,
    const float* __restrict__ Wb, const float* __restrict__ bb,
    float* __restrict__ out)
{
    float* sc   = smemB;            // 25600
    float* prj  = smemB + 25600;    // NT * PRJPAD
    float* eps  = smemB + 33920;    // PT * A_D
    float* wb2  = smemB + 34944;    // 512 float2 -> 1024 floats
    float* bbs  = smemB + 35968;    // 8
    int*   idxs = (int*)(smemB + 35976);

    const int bx   = blockIdx.x;
    const int b    = bx / 25;
    const int pt   = bx - b * 25;
    const int t    = threadIdx.x;
    const int p    = t >> 5;
    const int lane = t & 31;
    const int pg   = pt * PT + p;

    // ---- init loads -------------------------------------------------------
    for (int i = t; i < PT * A_D; i += 256) {
        int pl = i >> 7, a = i & 127;
        eps[i] = ept[(long)ptw[pt * PT + pl] * A_D + a];
    }
    for (int i = t; i < 512; i += 256) {          // (a2, h) pairs of Wb
        int a2 = i >> 3, h = i & 7;
        wb2[i * 2 + 0] = Wb[(2 * a2) * H_ + h];
        wb2[i * 2 + 1] = Wb[(2 * a2 + 1) * H_ + h];
    }
    if (t < 8) bbs[t] = bb[t];

    const u64* eps2 = (const u64*)(eps + p * A_D);
    const u64* wbp  = (const u64*)wb2;
    const u64  z2   = pack2(0.f, 0.f);

    // ---- Phase 1: scores --------------------------------------------------
    for (int n0 = 0; n0 < N_; n0 += NT) {
        __syncthreads();
        const int nvalid = min(NT, N_ - n0);
        const int tot2 = nvalid * (A_D / 2);
        for (int i = t; i < tot2; i += 256) {
            int r = i >> 6, c = i & 63;
            *(u64*)(prj + r * PRJPAD + 2 * c) =
                *(const u64*)(g_proj + (long)(b * N_ + n0 + r) * A_D + 2 * c);
        }
        __syncthreads();

        const int nA = n0 + lane;
        const int nB = n0 + 32 + lane;
        if (nA < N_) {
            const bool vB = (nB < N_);
            const u64* pA = (const u64*)(prj + lane * PRJPAD);
            const u64* pB = (const u64*)(prj + (32 + lane) * PRJPAD);
            u64 accA[H_], accB[H_];
#pragma unroll
            for (int h = 0; h < H_; h++) { accA[h] = z2; accB[h] = z2; }

            if (vB) {
#pragma unroll 4
                for (int a2 = 0; a2 < 64; a2++) {
                    u64 e2 = eps2[a2];
                    u64 tA = tanh2(add2(pA[a2], e2));
                    u64 tB = tanh2(add2(pB[a2], e2));
                    const u64* w = wbp + a2 * 8;
#pragma unroll
                    for (int h = 0; h < H_; h++) {
                        u64 ww = w[h];
                        accA[h] = fma2(tA, ww, accA[h]);
                        accB[h] = fma2(tB, ww, accB[h]);
                    }
                }
            } else {
#pragma unroll 4
                for (int a2 = 0; a2 < 64; a2++) {
                    u64 e2 = eps2[a2];
                    u64 tA = tanh2(add2(pA[a2], e2));
                    const u64* w = wbp + a2 * 8;
#pragma unroll
                    for (int h = 0; h < H_; h++)
                        accA[h] = fma2(tA, w[h], accA[h]);
                }
            }
#pragma unroll
            for (int h = 0; h < H_; h++) {
                float x, y;
                unpack2(accA[h], x, y);
                sc[(p * H_ + h) * N_ + nA] = x + y + bbs[h];
                if (vB) {
                    unpack2(accB[h], x, y);
                    sc[(p * H_ + h) * N_ + nB] = x + y + bbs[h];
                }
            }
        }
    }
    __syncthreads();   // all warps done reading prj chunks

    // ---- Phase 2: softmax over n per head, sum heads ----------------------
    float* scp = sc + p * H_ * N_;
    float invh[H_];
#pragma unroll
    for (int h = 0; h < H_; h++) {
        float* row = scp + h * N_;
        float m = -1e30f;
        for (int i = lane; i < N_; i += 32) m = fmaxf(m, row[i]);
#pragma unroll
        for (int o = 16; o; o >>= 1) m = fmaxf(m, __shfl_xor_sync(0xffffffffu, m, o));
        float s = 0.f;
        for (int i = lane; i < N_; i += 32) {
            float e = __expf(row[i] - m);
            row[i] = e;
            s += e;
        }
#pragma unroll
        for (int o = 16; o; o >>= 1) s += __shfl_xor_sync(0xffffffffu, s, o);
        invh[h] = 1.f / s;
    }
    float* attn = prj;              // reuse proj region: PT * N_ floats
    float* ap   = attn + p * N_;
    for (int i = lane; i < N_; i += 32) {
        float a = 0.f;
#pragma unroll
        for (int h = 0; h < H_; h++) a = fmaf(scp[h * N_ + i], invh[h], a);
        ap[i] = a;
    }

    // ---- Phase 3: pooling out[b,pg,:] = sum_n attn[p][n] * E[b,n,:] -------
    u64 acc[4];
#pragma unroll
    for (int k = 0; k < 4; k++) acc[k] = z2;

    for (int c = 0; c < 4; c++) {
        const int n0 = c * 100;
        __syncthreads();            // everyone done reading sc (scores/E chunk)
        if (t < 100) idxs[t] = omc[b * N_ + n0 + t];
        __syncthreads();
        float* Es = sc;             // 100 x 200 floats
        for (int i = t; i < 100 * 100; i += 256) {   // float2 elements
            int n = i / 100, e2 = i - n * 100;
            *(u64*)(Es + n * E_D + 2 * e2) =
                *(const u64*)(eg + (long)idxs[n] * E_D + 2 * e2);
        }
        __syncthreads();

#pragma unroll 2
        for (int n = 0; n < 100; n++) {
            float a = ap[n0 + n];                    // broadcast LDS
            u64 av = pack2(a, a);
            const u64* er = (const u64*)(Es + n * E_D);
            acc[0] = fma2(er[lane],      av, acc[0]);
            acc[1] = fma2(er[lane + 32], av, acc[1]);
            acc[2] = fma2(er[lane + 64], av, acc[2]);
            if (lane < 4) acc[3] = fma2(er[lane + 96], av, acc[3]);
        }
    }

    u64* op = (u64*)(out + ((long)(b * P_) + pg) * E_D);
    op[lane]      = acc[0];
    op[lane + 32] = acc[1];
    op[lane + 64] = acc[2];
    if (lane < 4) op[lane + 96] = acc[3];
}

// ---------------------------------------------------------------------------
extern "C" void kernel_launch(void* const* d_in, const int* in_sizes, int n_in,
                              void* d_out, int out_size)
{
    const int*   omc = (const int*)  d_in[0];
    const int*   ptw = (const int*)  d_in[1];
    const float* eg  = (const float*)d_in[2];
    const float* ept = (const float*)d_in[3];
    const float* W0  = (const float*)d_in[4];
    const float* b0  = (const float*)d_in[5];
    const float* Wb  = (const float*)d_in[6];
    const float* bb  = (const float*)d_in[7];
    float* out = (float*)d_out;

    kA<<<(B_ * N_) / 8, 128>>>(omc, eg, W0, b0);

    cudaFuncSetAttribute(kB, cudaFuncAttributeMaxDynamicSharedMemorySize,
                         SMEM_B_BYTES);
    kB<<<B_ * (P_ / PT), 256, SMEM_B_BYTES>>>(omc, ptw, eg, ept, Wb, bb, out);
}

// round 2
// speedup vs baseline: 1.2465x; 1.2465x over previous
#include <cuda_runtime.h>

#define B_    16
#define N_    400
#define P_    200
#define E_D   200
#define A_D   128
#define H_    8
#define PT    4      // pathways per block in kernel B

typedef unsigned long long u64;

// proj scratch, transposed pairs: g_projT[(b*64 + a2)*400 + n] = {proj[b,n,2a2], proj[b,n,2a2+1]}
__device__ u64 g_projT[B_ * 64 * N_];

__device__ __forceinline__ u64 pack2(float x, float y) {
    u64 r; asm("mov.b64 %0, {%1, %2};" : "=l"(r) : "f"(x), "f"(y)); return r;
}
__device__ __forceinline__ void unpack2(u64 v, float& x, float& y) {
    asm("mov.b64 {%0, %1}, %2;" : "=f"(x), "=f"(y) : "l"(v));
}
__device__ __forceinline__ u64 fma2(u64 a, u64 b, u64 c) {
    u64 d; asm("fma.rn.f32x2 %0, %1, %2, %3;" : "=l"(d) : "l"(a), "l"(b), "l"(c)); return d;
}
__device__ __forceinline__ u64 add2(u64 a, u64 b) {
    u64 d; asm("add.rn.f32x2 %0, %1, %2;" : "=l"(d) : "l"(a), "l"(b)); return d;
}
__device__ __forceinline__ float tanh_ap(float x) {
    float y; asm("tanh.approx.f32 %0, %1;" : "=f"(y) : "f"(x)); return y;
}
__device__ __forceinline__ u64 tanh2(u64 v) {
    float x, y; unpack2(v, x, y);
    return pack2(tanh_ap(x), tanh_ap(y));
}

// ---------------------------------------------------------------------------
// Kernel A: proj = emb_gene[omc] @ W0 + b0, written TRANSPOSED as float2 pairs.
// Block = 8 rows. 128 threads: t = (rg, k): k = a-pair 0..63, rg = row-group 0..1.
// ---------------------------------------------------------------------------
__global__ __launch_bounds__(128) void kA(
    const int* __restrict__ omc, const float* __restrict__ eg,
    const float* __restrict__ W0, const float* __restrict__ b0)
{
    __shared__ float EsT[E_D * 8];   // [e][r]
    __shared__ int idxs[8];
    const int R0 = blockIdx.x * 8;
    const int b  = R0 / N_;
    const int nb = R0 - b * N_;
    const int t  = threadIdx.x;

    if (t < 8) idxs[t] = omc[R0 + t];
    __syncthreads();
    for (int i = t; i < 8 * E_D; i += 128) {
        int r = i / E_D, e = i - r * E_D;
        EsT[e * 8 + r] = eg[(long)idxs[r] * E_D + e];
    }
    __syncthreads();

    const int k  = t & 63;           // a-pair
    const int rg = t >> 6;           // row group (4 rows each)
    const u64* W2 = (const u64*)W0;  // [e][64] pairs
    const u64  bias = ((const u64*)b0)[k];

    u64 acc[4];
#pragma unroll
    for (int r = 0; r < 4; r++) acc[r] = bias;

#pragma unroll 4
    for (int e = 0; e < E_D; e++) {
        u64 w = W2[e * 64 + k];
        const float* er = EsT + e * 8 + rg * 4;
        acc[0] = fma2(pack2(er[0], er[0]), w, acc[0]);
        acc[1] = fma2(pack2(er[1], er[1]), w, acc[1]);
        acc[2] = fma2(pack2(er[2], er[2]), w, acc[2]);
        acc[3] = fma2(pack2(er[3], er[3]), w, acc[3]);
    }
#pragma unroll
    for (int r = 0; r < 4; r++)
        g_projT[(long)(b * 64 + k) * N_ + nb + rg * 4 + r] = acc[r];
}

// ---------------------------------------------------------------------------
// Kernel B (fused). Block = (b, tile of 4 pathways), 256 threads = 8 warps.
// Warp w -> pathway p = w/2, half = w&1 (gene-half / head-half / E-half).
//
// SMEM floats:
//   sc   [0, 12800)      scores PT*H*N          (reused as E-chunk 64x200 in ph3)
//   attn [12800, 14400)  PT*N
//   eps  [14400, 14912)  PT*A
//   wb2  [14912, 15936)  512 u64-pairs of Wb (16B aligned for LDS.128)
//   sinv [15936, 15968)  PT*H
//   bbs  [15968, 15976)
//   idxs [15976, 16040)  64 ints
// = 64160 bytes -> 3 blocks/SM
// ---------------------------------------------------------------------------
#define SMEM_B_BYTES (16040 * 4)

extern __shared__ float smemB[];

__global__ __launch_bounds__(256, 3) void kB(
    const int* __restrict__ omc, const int* __restrict__ ptw,
    const float* __restrict__ eg, const float* __restrict__ ept,
    const float* __restrict__ Wb, const float* __restrict__ bb,
    float* __restrict__ out)
{
    float* sc   = smemB;
    float* attn = smemB + 12800;
    float* eps  = smemB + 14400;
    float* wb2  = smemB + 14912;
    float* sinv = smemB + 15936;
    float* bbs  = smemB + 15968;
    int*   idxs = (int*)(smemB + 15976);

    const int bx   = blockIdx.x;
    const int b    = bx / 50;
    const int pt   = bx - b * 50;
    const int t    = threadIdx.x;
    const int w    = t >> 5;
    const int lane = t & 31;
    const int p    = w >> 1;
    const int half = w & 1;
    const int pg   = pt * PT + p;

    // ---- init loads -------------------------------------------------------
    for (int i = t; i < PT * A_D; i += 256) {
        int pl = i >> 7, a = i & 127;
        eps[i] = ept[(long)ptw[pt * PT + pl] * A_D + a];
    }
    for (int i = t; i < 512; i += 256) {          // (a2, h) pairs of Wb
        int a2 = i >> 3, h = i & 7;
        wb2[i * 2 + 0] = Wb[(2 * a2) * H_ + h];
        wb2[i * 2 + 1] = Wb[(2 * a2 + 1) * H_ + h];
    }
    if (t < 8) bbs[t] = bb[t];
    __syncthreads();

    const u64* eps2 = (const u64*)(eps + p * A_D);   // 64 pairs
    const u64* wbp  = (const u64*)wb2;

    // ---- Phase 1: scores (no smem staging; coalesced LDG from g_projT) ----
    {
        float bh[H_];
#pragma unroll
        for (int h = 0; h < H_; h++) bh[h] = bbs[h];

        for (int k = 0; k < 7; k++) {
            const int gene = k * 64 + half * 32 + lane;
            if (gene < N_) {
                const u64* pp = g_projT + (long)b * 25600 + gene;  // + a2*400
                u64 acc[H_];
#pragma unroll
                for (int h = 0; h < H_; h++) acc[h] = 0ull;

#pragma unroll
                for (int a0 = 0; a0 < 64; a0 += 16) {
                    u64 pr[16];
#pragma unroll
                    for (int j = 0; j < 16; j++) pr[j] = pp[(a0 + j) * N_];
#pragma unroll
                    for (int j = 0; j < 16; j++) {
                        const int a2 = a0 + j;
                        u64 t2 = tanh2(add2(pr[j], eps2[a2]));
                        const ulonglong2* w2 = (const ulonglong2*)(wbp + a2 * 8);
                        ulonglong2 wA = w2[0], wB = w2[1], wC = w2[2], wD = w2[3];
                        acc[0] = fma2(t2, wA.x, acc[0]);
                        acc[1] = fma2(t2, wA.y, acc[1]);
                        acc[2] = fma2(t2, wB.x, acc[2]);
                        acc[3] = fma2(t2, wB.y, acc[3]);
                        acc[4] = fma2(t2, wC.x, acc[4]);
                        acc[5] = fma2(t2, wC.y, acc[5]);
                        acc[6] = fma2(t2, wD.x, acc[6]);
                        acc[7] = fma2(t2, wD.y, acc[7]);
                    }
                }
#pragma unroll
                for (int h = 0; h < H_; h++) {
                    float x, y;
                    unpack2(acc[h], x, y);
                    sc[(p * H_ + h) * N_ + gene] = x + y + bh[h];
                }
            }
        }
    }
    __syncthreads();

    // ---- Phase 2: softmax over n per head; attn = sum_h ------------------
    float* scp = sc + p * H_ * N_;
#pragma unroll
    for (int q = 0; q < 4; q++) {
        const int h = half * 4 + q;
        float* row = scp + h * N_;
        float m = -1e30f;
        for (int i = lane; i < N_; i += 32) m = fmaxf(m, row[i]);
#pragma unroll
        for (int o = 16; o; o >>= 1) m = fmaxf(m, __shfl_xor_sync(0xffffffffu, m, o));
        float s = 0.f;
        for (int i = lane; i < N_; i += 32) {
            float e = __expf(row[i] - m);
            row[i] = e;
            s += e;
        }
#pragma unroll
        for (int o = 16; o; o >>= 1) s += __shfl_xor_sync(0xffffffffu, s, o);
        if (lane == 0) sinv[p * H_ + h] = __fdividef(1.f, s);
    }
    __syncthreads();

    {
        float iv[H_];
#pragma unroll
        for (int h = 0; h < H_; h++) iv[h] = sinv[p * H_ + h];
        for (int i = lane; i < 200; i += 32) {
            const int n = half * 200 + i;
            float a = 0.f;
#pragma unroll
            for (int h = 0; h < H_; h++) a = fmaf(scp[h * N_ + n], iv[h], a);
            attn[p * N_ + n] = a;
        }
    }

    // ---- Phase 3: out[b,pg,:] = sum_n attn[n] * E[b,n,:] ------------------
    const u64* eg2 = (const u64*)eg;        // 100 u64 per vocab row
    u64* Es = (u64*)sc;                     // 64 genes x 100 u64 (fits exactly)
    const float* ap = attn + p * N_;
    const int j0 = half * 50;               // this warp's E-slice (u64 units)
    u64 acc0 = 0ull, acc1 = 0ull;

    for (int c = 0; c < 7; c++) {
        const int n0 = c * 64;
        const int cnt = min(64, N_ - n0);
        __syncthreads();                    // protect Es/idxs reuse
        if (t < cnt) idxs[t] = omc[b * N_ + n0 + t];
        __syncthreads();
        for (int i = t; i < cnt * 100; i += 256) {
            int n = i / 100, e2 = i - n * 100;
            Es[n * 100 + e2] = eg2[(long)idxs[n] * 100 + e2];
        }
        __syncthreads();

#pragma unroll 2
        for (int n = 0; n < cnt; n++) {
            float a = ap[n0 + n];
            u64 av = pack2(a, a);
            const u64* er = Es + n * 100;
            acc0 = fma2(er[j0 + lane], av, acc0);
            if (lane < 18) acc1 = fma2(er[j0 + 32 + lane], av, acc1);
        }
    }

    u64* op = (u64*)out + (long)(b * P_ + pg) * 100;
    op[j0 + lane] = acc0;
    if (lane < 18) op[j0 + 32 + lane] = acc1;
}

// ---------------------------------------------------------------------------
extern "C" void kernel_launch(void* const* d_in, const int* in_sizes, int n_in,
                              void* d_out, int out_size)
{
    const int*   omc = (const int*)  d_in[0];
    const int*   ptw = (const int*)  d_in[1];
    const float* eg  = (const float*)d_in[2];
    const float* ept = (const float*)d_in[3];
    const float* W0  = (const float*)d_in[4];
    const float* b0  = (const float*)d_in[5];
    const float* Wb  = (const float*)d_in[6];
    const float* bb  = (const float*)d_in[7];
    float* out = (float*)d_out;

    kA<<<(B_ * N_) / 8, 128>>>(omc, eg, W0, b0);

    cudaFuncSetAttribute(kB, cudaFuncAttributeMaxDynamicSharedMemorySize,
                         SMEM_B_BYTES);
    kB<<<B_ * (P_ / PT), 256, SMEM_B_BYTES>>>(omc, ptw, eg, ept, Wb, bb, out);
}